// round 11
// baseline (speedup 1.0000x reference)
#include <cuda_runtime.h>

#define NN 100000
#define NE 3200000
#define NF 128
#define NH 16
#define MH 100
#define NC 12
#define NG 512
#define NBLK 391        // ceil(NN/256)
#define FILL4BLK 3125   // NE / (256*4)
#define CSRCAP (NE + 3 * NN)   // rowstarts padded to multiples of 4

// ---- device scratch (static, no allocation; 16B-aligned).
// g_deg / g_pooled: zero-init by CUDA, re-zeroed by last reader per launch.
__device__ __align__(16) int   g_csr[CSRCAP];     // src index only
__device__ __align__(16) int   g_deg[NN];
__device__ __align__(16) int   g_rowstart[NN];
__device__ __align__(16) int   g_cursor[NN];
__device__ __align__(16) int   g_blocksum[512];
__device__ __align__(16) float g_dinv[NN];
__device__ __align__(16) float g_hpre[NN * NH];   // dinv * (x @ W1)
__device__ __align__(16) float g_hpre2[NN * NH];  // dinv * (h1 @ W2)
__device__ __align__(16) float g_pooled[NG * NH];

__device__ __forceinline__ void red4(float* p, float4 v) {
    asm volatile("red.global.add.v4.f32 [%0], {%1,%2,%3,%4};"
                 :: "l"(p), "f"(v.x), "f"(v.y), "f"(v.z), "f"(v.w)
                 : "memory");
}
__device__ __forceinline__ float4 fma4(float s, float4 a, float4 acc) {
    acc.x = fmaf(s, a.x, acc.x); acc.y = fmaf(s, a.y, acc.y);
    acc.z = fmaf(s, a.z, acc.z); acc.w = fmaf(s, a.w, acc.w);
    return acc;
}
__device__ __forceinline__ float4 add4(float4 a, float4 b) {
    a.x += b.x; a.y += b.y; a.z += b.z; a.w += b.w; return a;
}
// int64 buffers viewed as int32 are [v,0,v,0,...]; sample odd words of the
// EDGE INDEX ONLY (batch_vec is sorted -> leading zeros legitimate there).
__device__ __forceinline__ int probe64(const int* p32) {
    int nz = 0;
#pragma unroll
    for (int k = 1; k < 16; k += 2) nz |= p32[k];
    return nz == 0;
}
// load 4 consecutive edge indices at position e (e % 4 == 0)
__device__ __forceinline__ int4 ld4idx(const void* col, int e, int is64) {
    if (is64) {
        ulonglong2 a = __ldg((const ulonglong2*)((const long long*)col + e));
        ulonglong2 b = __ldg((const ulonglong2*)((const long long*)col + e) + 1);
        return make_int4((int)a.x, (int)a.y, (int)b.x, (int)b.y);
    }
    return __ldg((const int4*)((const int*)col + e));
}

// ---- degree count, 4 edges/thread (atomic MLP=4) ----
__global__ __launch_bounds__(256) void k_deg(const void* __restrict__ ei) {
    __shared__ int is64s;
    if (threadIdx.x == 0) is64s = probe64((const int*)ei);
    __syncthreads();
    int e = (blockIdx.x * 256 + threadIdx.x) * 4;
    if (e >= NE) return;
    const void* dstcol = is64s ? (const void*)((const long long*)ei + NE)
                               : (const void*)((const int*)ei + NE);
    int4 d = ld4idx(dstcol, e, is64s);
    atomicAdd(&g_deg[d.x], 1);
    atomicAdd(&g_deg[d.y], 1);
    atomicAdd(&g_deg[d.z], 1);
    atomicAdd(&g_deg[d.w], 1);
}

// ---- scanA: per-block sums of padded degrees ----
__global__ void k_scanA() {
    __shared__ int s[256];
    int i = blockIdx.x * 256 + threadIdx.x;
    s[threadIdx.x] = (i < NN) ? ((g_deg[i] + 3) & ~3) : 0;
    __syncthreads();
    for (int o = 128; o > 0; o >>= 1) {
        if (threadIdx.x < o) s[threadIdx.x] += s[threadIdx.x + o];
        __syncthreads();
    }
    if (threadIdx.x == 0) g_blocksum[blockIdx.x] = s[0];
}

// ---- scanB: block-offset reduction + local scan -> rowstart/cursor/dinv ----
__global__ void k_scanB() {
    __shared__ int s[256];
    __shared__ int off;
    int t = threadIdx.x;
    int b = blockIdx.x;
    int v = 0;
    if (t < b) v = g_blocksum[t];
    if (t + 256 < b) v += g_blocksum[t + 256];
    s[t] = v;
    __syncthreads();
    for (int o = 128; o > 0; o >>= 1) {
        if (t < o) s[t] += s[t + o];
        __syncthreads();
    }
    if (t == 0) off = s[0];
    __syncthreads();
    int i = b * 256 + t;
    int d  = (i < NN) ? g_deg[i] : 0;
    int d4 = (d + 3) & ~3;
    s[t] = d4;
    __syncthreads();
    for (int o = 1; o < 256; o <<= 1) {
        int vv = (t >= o) ? s[t - o] : 0;
        __syncthreads();
        s[t] += vv;
        __syncthreads();
    }
    if (i < NN) {
        int start = off + s[t] - d4;
        g_rowstart[i] = start;
        g_cursor[i]   = start;
        g_dinv[i]     = rsqrtf((float)(d + 1));
    }
}

// ---- fused fill + gemm1, interleaved (every 9th block is a gemm block) ----
// fill: 4 edges/thread, csr[slot] = src (4B), atomic MLP=4
// gemm: hpre[r] = dinv[r] * (x[r] @ W1)
__global__ __launch_bounds__(256) void k_fillgemm(const float* __restrict__ x,
                                                  const float* __restrict__ W1,
                                                  const void* __restrict__ ei) {
    int g = blockIdx.x;
    bool is_gemm = (g % 9 == 0) && (g / 9 < NBLK);
    if (!is_gemm) {
        __shared__ int is64s;
        if (threadIdx.x == 0) is64s = probe64((const int*)ei);
        __syncthreads();
        int fb = g - g / 9 - 1;            // fill block index 0..FILL4BLK-1
        int e = (fb * 256 + threadIdx.x) * 4;
        if (e >= NE) return;
        const void* dstcol = is64s ? (const void*)((const long long*)ei + NE)
                                   : (const void*)((const int*)ei + NE);
        int4 s = ld4idx(ei, e, is64s);
        int4 d = ld4idx(dstcol, e, is64s);
        int s0 = atomicAdd(&g_cursor[d.x], 1);
        int s1 = atomicAdd(&g_cursor[d.y], 1);
        int s2 = atomicAdd(&g_cursor[d.z], 1);
        int s3 = atomicAdd(&g_cursor[d.w], 1);
        g_csr[s0] = s.x;
        g_csr[s1] = s.y;
        g_csr[s2] = s.z;
        g_csr[s3] = s.w;
        return;
    }
    // gemm part
    __shared__ float4 w4[NF * 4];   // w4[k*4+q] = W1[k][4q..4q+3]
    for (int i = threadIdx.x; i < NF * 4; i += blockDim.x)
        w4[i] = ((const float4*)W1)[i];
    __syncthreads();
    int r = (g / 9) * 256 + threadIdx.x;
    if (r >= NN) return;
    float4 a0 = make_float4(0.f, 0.f, 0.f, 0.f);
    float4 a1 = a0, a2 = a0, a3 = a0;
    const float4* xr = (const float4*)(x + (size_t)r * NF);
#pragma unroll 4
    for (int k4 = 0; k4 < NF / 4; k4++) {
        float4 xv = __ldg(xr + k4);
        const float4* wr = &w4[(4 * k4) * 4];
        a0 = fma4(xv.x, wr[0], a0); a1 = fma4(xv.x, wr[1], a1);
        a2 = fma4(xv.x, wr[2], a2); a3 = fma4(xv.x, wr[3], a3);
        a0 = fma4(xv.y, wr[4], a0); a1 = fma4(xv.y, wr[5], a1);
        a2 = fma4(xv.y, wr[6], a2); a3 = fma4(xv.y, wr[7], a3);
        a0 = fma4(xv.z, wr[8], a0); a1 = fma4(xv.z, wr[9], a1);
        a2 = fma4(xv.z, wr[10], a2); a3 = fma4(xv.z, wr[11], a3);
        a0 = fma4(xv.w, wr[12], a0); a1 = fma4(xv.w, wr[13], a1);
        a2 = fma4(xv.w, wr[14], a2); a3 = fma4(xv.w, wr[15], a3);
    }
    float di = g_dinv[r];
    float4 z = make_float4(0.f, 0.f, 0.f, 0.f);
    float4* o = (float4*)(g_hpre + (size_t)r * NH);
    o[0] = fma4(di, a0, z);
    o[1] = fma4(di, a1, z);
    o[2] = fma4(di, a2, z);
    o[3] = fma4(di, a3, z);
}

// ---- fused agg+fin, 4 threads per dst (f4 = feature chunk), int4 index reads ----
// out_pre[d] = dinv[d] * (sum_{s in N(d)} hs[s] + hs[d])
// LAYER 1: h = relu(out_pre + b1); hpre2 = dinv[d] * (h @ W2)  (shuffle-based)
// LAYER 2: v = relu(out_pre + b2); pool via red4; re-zero g_deg
template <int LAYER>
__global__ __launch_bounds__(256) void k_aggfin(const float* __restrict__ bias,
                                                const float* __restrict__ W2,
                                                const void* __restrict__ batch,
                                                const void* __restrict__ ei) {
    __shared__ float4 w2s4[NH * 4];   // [j*4+q] = W2[j][4q..4q+3]
    __shared__ float bs[NH];
    __shared__ int is64s;
    if (LAYER == 1 && threadIdx.x < NH * 4) w2s4[threadIdx.x] = ((const float4*)W2)[threadIdx.x];
    if (threadIdx.x < NH) bs[threadIdx.x] = bias[threadIdx.x];
    if (LAYER == 2 && threadIdx.x == 0) is64s = probe64((const int*)ei);  // probe EI, not batch
    __syncthreads();

    int tid = blockIdx.x * blockDim.x + threadIdx.x;
    int dst = tid >> 2;
    int f4  = tid & 3;
    if (dst >= NN) return;
    int start = __ldg(&g_rowstart[dst]);
    int cnt   = __ldg(&g_deg[dst]);
    if (LAYER == 2 && f4 == 0) g_deg[dst] = 0;   // self-restore for next launch
    const float* hin = (LAYER == 1 ? g_hpre : g_hpre2);
    const int4* p4 = (const int4*)(g_csr + start);   // start is 4-aligned
    float4 acc = make_float4(0.f, 0.f, 0.f, 0.f);
    float4 acc2 = acc;
    int n4 = cnt >> 2;
    for (int k = 0; k < n4; k++) {
        int4 e = __ldg(p4 + k);
        float4 v0 = __ldg((const float4*)(hin + (size_t)e.x * NH) + f4);
        float4 v1 = __ldg((const float4*)(hin + (size_t)e.y * NH) + f4);
        float4 v2 = __ldg((const float4*)(hin + (size_t)e.z * NH) + f4);
        float4 v3 = __ldg((const float4*)(hin + (size_t)e.w * NH) + f4);
        acc  = add4(acc,  add4(v0, v1));
        acc2 = add4(acc2, add4(v2, v3));
    }
    const int* ps = g_csr + start;
    for (int i = n4 << 2; i < cnt; i++) {
        int s = __ldg(ps + i);
        acc = add4(acc, __ldg((const float4*)(hin + (size_t)s * NH) + f4));
    }
    acc = add4(acc, acc2);
    // self loop, then scale by dinv[dst], bias, relu
    acc = add4(acc, __ldg((const float4*)(hin + (size_t)dst * NH) + f4));
    float di = g_dinv[dst];
    float h[4];
    h[0] = fmaxf(fmaf(di, acc.x, bs[4 * f4 + 0]), 0.f);
    h[1] = fmaxf(fmaf(di, acc.y, bs[4 * f4 + 1]), 0.f);
    h[2] = fmaxf(fmaf(di, acc.z, bs[4 * f4 + 2]), 0.f);
    h[3] = fmaxf(fmaf(di, acc.w, bs[4 * f4 + 3]), 0.f);

    if (LAYER == 1) {
        // o[4*f4..] = sum_j h_full[j] * W2[j][4*f4..]; gather h_full via group shuffles
        int lane = threadIdx.x & 31;
        int base = lane & ~3;
        unsigned gmask = 0xFu << base;
        float4 o = make_float4(0.f, 0.f, 0.f, 0.f);
#pragma unroll
        for (int l = 0; l < 4; l++) {
#pragma unroll
            for (int m = 0; m < 4; m++) {
                float hv = __shfl_sync(gmask, h[m], base + l, 32);
                o = fma4(hv, w2s4[(4 * l + m) * 4 + f4], o);
            }
        }
        // pre-scale for layer 2: hpre2 = dinv[d] * (h1 @ W2)
        o.x *= di; o.y *= di; o.z *= di; o.w *= di;
        ((float4*)(g_hpre2 + (size_t)dst * NH))[f4] = o;
    } else {
        int b = is64s ? (int)((const long long*)batch)[dst] : ((const int*)batch)[dst];
        red4(g_pooled + (size_t)b * NH + 4 * f4, make_float4(h[0], h[1], h[2], h[3]));
    }
}

// ---- MLP head (re-zeroes g_pooled after reading) ----
__global__ void k_head(const float* __restrict__ lw1, const float* __restrict__ lb1,
                       const float* __restrict__ lw2, const float* __restrict__ lb2,
                       float* __restrict__ out) {
    __shared__ float w1s[NH * MH];
    __shared__ float w2s[MH * NC];
    __shared__ float b1s[MH];
    __shared__ float b2s[NC];
    for (int i = threadIdx.x; i < NH * MH; i += blockDim.x) w1s[i] = lw1[i];
    for (int i = threadIdx.x; i < MH * NC; i += blockDim.x) w2s[i] = lw2[i];
    if (threadIdx.x < MH) b1s[threadIdx.x] = lb1[threadIdx.x];
    if (threadIdx.x < NC) b2s[threadIdx.x] = lb2[threadIdx.x];
    __syncthreads();
    int g = blockIdx.x * blockDim.x + threadIdx.x;
    if (g >= NG) return;
    float p[NH];
#pragma unroll
    for (int j = 0; j < NH; j++) {
        p[j] = fmaxf(g_pooled[g * NH + j], 0.f);
        g_pooled[g * NH + j] = 0.f;   // self-restore for next launch
    }
    float o[NC];
#pragma unroll
    for (int c = 0; c < NC; c++) o[c] = b2s[c];
    for (int m = 0; m < MH; m++) {
        float hh = b1s[m];
#pragma unroll
        for (int j = 0; j < NH; j++) hh += p[j] * w1s[j * MH + m];
        hh = fmaxf(hh, 0.f);
#pragma unroll
        for (int c = 0; c < NC; c++) o[c] += hh * w2s[m * NC + c];
    }
#pragma unroll
    for (int c = 0; c < NC; c++) out[g * NC + c] = o[c];
}

extern "C" void kernel_launch(void* const* d_in, const int* in_sizes, int n_in,
                              void* d_out, int out_size) {
    const float* x = nullptr;
    const void*  ei = nullptr;
    const void*  batch = nullptr;
    const float *W1 = nullptr, *b1 = nullptr, *W2 = nullptr, *b2 = nullptr;
    const float *lw1 = nullptr, *lb1 = nullptr, *lw2 = nullptr, *lb2 = nullptr;
    for (int i = 0; i < n_in; i++) {
        int sz = in_sizes[i];
        const void* p = d_in[i];
        switch (sz) {
            case NN * NF:   x     = (const float*)p; break;
            case 2 * NE:    ei    = p; break;
            case NN:        batch = p; break;
            case NF * NH:   W1    = (const float*)p; break;
            case NH * NH:   W2    = (const float*)p; break;
            case NH * MH:   lw1   = (const float*)p; break;
            case MH:        lb1   = (const float*)p; break;
            case MH * NC:   lw2   = (const float*)p; break;
            case NC:        lb2   = (const float*)p; break;
            case NH:        if (!b1) b1 = (const float*)p; else b2 = (const float*)p; break;
            default: break;
        }
    }
    float* out = (float*)d_out;

    k_deg<<<FILL4BLK, 256>>>(ei);
    k_scanA<<<NBLK, 256>>>();
    k_scanB<<<NBLK, 256>>>();
    k_fillgemm<<<FILL4BLK + NBLK, 256>>>(x, W1, ei);
    k_aggfin<1><<<(NN * 4 + 255) / 256, 256>>>(b1, W2, nullptr, nullptr);
    k_aggfin<2><<<(NN * 4 + 255) / 256, 256>>>(b2, nullptr, batch, ei);
    k_head<<<(NG + 255) / 256, 256>>>(lw1, lb1, lw2, lb2, out);
}